// round 16
// baseline (speedup 1.0000x reference)
#include <cuda_runtime.h>
#include <cstdint>

// Problem constants
#define B_SZ   1024
#define F_SZ   784
#define OUT_F  1024
#define OR_T   32
#define AND_T  16
#define NLIT   (1 + 2 * F_SZ)   // 1569 literals
#define HBG    16               // batch-groups per half (512 batches)

// Split table: g_T2[h][idx][bgl], rows of 16 words (64B).
#define HALF_WORDS (NLIT * HBG)              // 25104 words = 100416 B
#define HALF_BYTES (HALF_WORDS * 4)          // 100416 = 16 * 6276
#define CHUNK_BYTES (HALF_BYTES / 4)         // 25104 = 16 * 1569
__device__ __align__(16) uint32_t g_T2[2 * HALF_WORDS];

#define OUTS_PER_BLOCK 8
#define NTHREADS 512
#define CLUSTER_SZ 4
#define W_WORDS (OUTS_PER_BLOCK * OR_T * AND_T)     // 4096 words = 16 KB
#define RES_WORDS (OUTS_PER_BLOCK * 2 * HBG)        // 256 words
#define MBAR_OFF_W (2 * HALF_WORDS + W_WORDS + RES_WORDS)  // 54560 (16B ok)
#define SMEM_BYTES ((MBAR_OFF_W + 8) * 4)           // ~218.3 KB

// ---------------------------------------------------------------------------
// Pack kernel: grid (25, 32), 128 threads. Dual-polarity, batch-split table.
// ---------------------------------------------------------------------------
__global__ __launch_bounds__(128) void pack_kernel(const float* __restrict__ x) {
    __shared__ float tile[32][33];

    const int ft  = blockIdx.x;
    const int bg  = blockIdx.y;               // 0..31
    const int tid = threadIdx.x;
    const int f0  = ft * 32;

    const int c  = tid & 31;
    const int r0 = tid >> 5;
    #pragma unroll
    for (int r = r0; r < 32; r += 4) {
        const int f = f0 + c;
        tile[r][c] = (f < F_SZ) ? x[(size_t)(bg * 32 + r) * F_SZ + f] : 0.0f;
    }
    __syncthreads();

    const int h    = bg >> 4;
    const int bgl  = bg & 15;
    uint32_t* base = g_T2 + (size_t)h * HALF_WORDS + bgl;

    const int lane = tid & 31;
    const int w    = tid >> 5;
    #pragma unroll
    for (int ff = w; ff < 32; ff += 4) {
        const int f = f0 + ff;
        if (f >= F_SZ) break;
        uint32_t m = __ballot_sync(0xFFFFFFFFu, tile[lane][ff] != 0.0f);
        if (lane == 0) {
            base[(size_t)(1 + f) * HBG]        = m;
            base[(size_t)(1 + F_SZ + f) * HBG] = ~m;
        }
    }
    if (ft == 0 && tid == 0) base[0] = 0xFFFFFFFFu;   // const-true row
}

// ---------------------------------------------------------------------------
// Logic kernel: 128 blocks (clusters of 4) x 512 threads.
//  - Table in two 100KB batch-halves, each with its own mbarrier; the cluster
//    leader multicasts half A's 4 chunks, then half B's. Warp (o, h) waits
//    only on its half -> gather overlaps the other half's fill.
//  - Weights staged via plain LDG->STS during the fill (no barrier needed).
//  - Gather: lane = (tq = lane>>2 term-of-8, bq = lane&3 uint4-of-row).
//    LDS.128 gathers retire 4 batch-groups each; 4 passes x 8 terms = 32.
// ---------------------------------------------------------------------------
__global__ __launch_bounds__(NTHREADS, 1) __cluster_dims__(CLUSTER_SZ, 1, 1)
void logic_kernel(const int* __restrict__ weights, float* __restrict__ out) {

    extern __shared__ uint32_t smem[];
    uint32_t* sT   = smem;                     // two halves (50208 words)
    uint32_t* sw   = smem + 2 * HALF_WORDS;    // weights (4096 words)
    uint32_t* resb = sw + W_WORDS;             // results (256 words)
    uint32_t  mbarA, mbarB;
    {
        uint64_t* mb64 = (uint64_t*)(smem + MBAR_OFF_W);
        asm("{ .reg .u64 t; cvta.to.shared.u64 t, %1; cvt.u32.u64 %0, t; }"
            : "=r"(mbarA) : "l"((void*)mb64));
        mbarB = mbarA + 8;
    }

    const int tid   = threadIdx.x;
    const int oBase = blockIdx.x * OUTS_PER_BLOCK;
    uint32_t rank;
    asm("mov.u32 %0, %%cluster_ctarank;" : "=r"(rank));

    if (tid == 0) {
        asm volatile("mbarrier.init.shared.b64 [%0], 1;" :: "r"(mbarA) : "memory");
        asm volatile("mbarrier.init.shared.b64 [%0], 1;" :: "r"(mbarB) : "memory");
    }
    __syncthreads();
    if (tid == 0) {
        asm volatile("mbarrier.arrive.expect_tx.shared.b64 _, [%0], %1;"
                     :: "r"(mbarA), "r"((uint32_t)HALF_BYTES) : "memory");
        asm volatile("mbarrier.arrive.expect_tx.shared.b64 _, [%0], %1;"
                     :: "r"(mbarB), "r"((uint32_t)HALF_BYTES) : "memory");
    }
    // All cluster mbarriers ready before any multicast lands
    asm volatile("barrier.cluster.arrive.aligned;" ::: "memory");
    asm volatile("barrier.cluster.wait.aligned;"   ::: "memory");

    if (tid == 0 && rank == 0) {
        uint32_t sdst;
        asm("{ .reg .u64 t; cvta.to.shared.u64 t, %1; cvt.u32.u64 %0, t; }"
            : "=r"(sdst) : "l"((void*)sT));
        const char* gsrc = (const char*)g_T2;
        const uint16_t mask = (uint16_t)((1u << CLUSTER_SZ) - 1u);
        // Half A chunks first (priority), completing mbarA early
        #pragma unroll
        for (int i = 0; i < 4; ++i) {
            asm volatile(
                "cp.async.bulk.shared::cluster.global.mbarrier::complete_tx::bytes"
                ".multicast::cluster [%0], [%1], %2, [%3], %4;"
                :: "r"(sdst + i * CHUNK_BYTES), "l"(gsrc + (size_t)i * CHUNK_BYTES),
                   "r"((uint32_t)CHUNK_BYTES), "r"(mbarA), "h"(mask) : "memory");
        }
        #pragma unroll
        for (int i = 4; i < 8; ++i) {
            asm volatile(
                "cp.async.bulk.shared::cluster.global.mbarrier::complete_tx::bytes"
                ".multicast::cluster [%0], [%1], %2, [%3], %4;"
                :: "r"(sdst + i * CHUNK_BYTES), "l"(gsrc + (size_t)i * CHUNK_BYTES),
                   "r"((uint32_t)CHUNK_BYTES), "r"(mbarB), "h"(mask) : "memory");
        }
    }

    // Stage weights via LDG->STS while the DMA streams (2 uint4 per thread)
    {
        const uint4* wsrc = (const uint4*)(weights + (size_t)oBase * OR_T * AND_T);
        uint4* wdst = (uint4*)sw;
        wdst[tid]            = wsrc[tid];
        wdst[tid + NTHREADS] = wsrc[tid + NTHREADS];
    }
    __syncthreads();   // weights visible to all warps

    const int wid  = tid >> 5;                 // 0..15
    const int lane = tid & 31;
    const int o    = wid >> 1;                 // output within block (0..7)
    const int h    = wid & 1;                  // batch half
    const int tq   = lane >> 2;                // term-of-8 (0..7)
    const int bq   = lane & 3;                 // uint4 within 64B row

    // Wait only on this warp's half
    {
        const uint32_t mb = h ? mbarB : mbarA;
        uint32_t done;
        asm volatile(
            "{\n\t.reg .pred p;\n\t"
            "mbarrier.try_wait.parity.acquire.cta.shared::cta.b64 p, [%1], 0;\n\t"
            "selp.b32 %0, 1, 0, p;\n\t}"
            : "=r"(done) : "r"(mb) : "memory");
        if (!done) {
            asm volatile(
                "{\n\t.reg .pred P1;\n\t"
                "WL_%=:\n\t"
                "mbarrier.try_wait.parity.acquire.cta.shared::cta.b64 P1, [%0], 0, 0x989680;\n\t"
                "@P1 bra.uni WD_%=;\n\t"
                "bra.uni WL_%=;\n\t"
                "WD_%=:\n\t}"
                :: "r"(mb) : "memory");
        }
    }

    const uint4* sTh = (const uint4*)(sT + (size_t)h * HALF_WORDS);  // rows: 4 uint4
    const uint32_t* swb = sw + o * (OR_T * AND_T);

    #define GV(i) sTh[(i) * 4 + bq]            // LDS.128: 4 batch-groups

    uint4 res = make_uint4(0u, 0u, 0u, 0u);
    #pragma unroll
    for (int p = 0; p < 4; ++p) {
        const int term = p * 8 + tq;
        const uint4* tw4 = (const uint4*)(swb + term * AND_T);
        const uint4 w0 = tw4[0], w1 = tw4[1], w2 = tw4[2], w3 = tw4[3];
        const uint32_t orw = (w0.x | w0.y | w0.z | w0.w) | (w1.x | w1.y | w1.z | w1.w)
                           | (w2.x | w2.y | w2.z | w2.w) | (w3.x | w3.y | w3.z | w3.w);

        uint4 a = GV(w0.x), b = GV(w0.y), c = GV(w0.z), d = GV(w0.w);
        uint4 m0, m1;
        m0.x = a.x & c.x; m0.y = a.y & c.y; m0.z = a.z & c.z; m0.w = a.w & c.w;
        m1.x = b.x & d.x; m1.y = b.y & d.y; m1.z = b.z & d.z; m1.w = b.w & d.w;
        a = GV(w1.x); b = GV(w1.y); c = GV(w1.z); d = GV(w1.w);
        m0.x &= a.x & c.x; m0.y &= a.y & c.y; m0.z &= a.z & c.z; m0.w &= a.w & c.w;
        m1.x &= b.x & d.x; m1.y &= b.y & d.y; m1.z &= b.z & d.z; m1.w &= b.w & d.w;
        a = GV(w2.x); b = GV(w2.y); c = GV(w2.z); d = GV(w2.w);
        m0.x &= a.x & c.x; m0.y &= a.y & c.y; m0.z &= a.z & c.z; m0.w &= a.w & c.w;
        m1.x &= b.x & d.x; m1.y &= b.y & d.y; m1.z &= b.z & d.z; m1.w &= b.w & d.w;
        a = GV(w3.x); b = GV(w3.y); c = GV(w3.z); d = GV(w3.w);
        m0.x &= a.x & c.x; m0.y &= a.y & c.y; m0.z &= a.z & c.z; m0.w &= a.w & c.w;
        m1.x &= b.x & d.x; m1.y &= b.y & d.y; m1.z &= b.z & d.z; m1.w &= b.w & d.w;

        const uint32_t sel = (orw != 0) ? ~0u : 0u;
        res.x |= m0.x & m1.x & sel;
        res.y |= m0.y & m1.y & sel;
        res.z |= m0.z & m1.z & sel;
        res.w |= m0.w & m1.w & sel;
    }
    #undef GV

    // OR-reduce across the 8 tq groups (lanes +-4, +-8, +-16 share bq)
    #pragma unroll
    for (int d = 4; d <= 16; d <<= 1) {
        res.x |= __shfl_xor_sync(0xFFFFFFFFu, res.x, d);
        res.y |= __shfl_xor_sync(0xFFFFFFFFu, res.y, d);
        res.z |= __shfl_xor_sync(0xFFFFFFFFu, res.z, d);
        res.w |= __shfl_xor_sync(0xFFFFFFFFu, res.w, d);
    }
    if (lane < 4) {
        ((uint4*)resb)[(o * 2 + h) * 4 + bq] = res;   // 16 words per (o,h)
    }
    __syncthreads();

    // Store: per batch, 8 contiguous floats (two float4)
    #pragma unroll
    for (int b = tid; b < B_SZ; b += NTHREADS) {      // 2 iterations
        const int bg  = b >> 5;
        const int h2  = bg >> 4;
        const int lbg = bg & 15;
        const int j   = b & 31;
        float4 v0, v1;
        #define GETBIT(ow) ((resb[((ow) * 2 + h2) * HBG + lbg] >> j) & 1u)
        v0.x = (float)GETBIT(0); v0.y = (float)GETBIT(1);
        v0.z = (float)GETBIT(2); v0.w = (float)GETBIT(3);
        v1.x = (float)GETBIT(4); v1.y = (float)GETBIT(5);
        v1.z = (float)GETBIT(6); v1.w = (float)GETBIT(7);
        #undef GETBIT
        float4* dst = (float4*)(out + (size_t)b * OUT_F + oBase);
        dst[0] = v0;
        dst[1] = v1;
    }
}

// ---------------------------------------------------------------------------
extern "C" void kernel_launch(void* const* d_in, const int* in_sizes, int n_in,
                              void* d_out, int out_size) {
    const float* x       = (const float*)d_in[0];   // (1024, 784) float32
    const int*   weights = (const int*)d_in[1];     // (1024, 32, 16) int32
    float*       out     = (float*)d_out;           // (1024, 1024) float32

    cudaFuncSetAttribute(logic_kernel,
                         cudaFuncAttributeMaxDynamicSharedMemorySize, SMEM_BYTES);

    dim3 pgrid(25, 32);
    pack_kernel<<<pgrid, 128>>>(x);
    logic_kernel<<<OUT_F / OUTS_PER_BLOCK, NTHREADS, SMEM_BYTES>>>(weights, out);
}